// round 1
// baseline (speedup 1.0000x reference)
#include <cuda_runtime.h>
#include <cuda_bf16.h>
#include <cstdint>

#define DIN 1024
#define DH  256
#define NC  8

#define BM 128
#define BN 256
#define BK 32
#define NT 512          // threads in main kernel
#define SAU 20          // u32 row stride for smem tiles (40 bf16 = padded BK)
#define SPS 264         // padded stride for per-cluster partials

__device__ float g_csum[NC * DH];
__device__ int   g_cnt[NC];
__device__ __align__(16) __nv_bfloat16 g_w1bf[DH * DIN];

// ---------------- W1 fp32 -> bf16 ----------------
__global__ void k_convert(const float* __restrict__ W1) {
    int i = blockIdx.x * blockDim.x + threadIdx.x;
    int stride = gridDim.x * blockDim.x;
    for (; i < DH * DIN; i += stride)
        g_w1bf[i] = __float2bfloat16(W1[i]);
}

// ---------------- cluster counts ----------------
__global__ void k_count(const int* __restrict__ cid, int n) {
    __shared__ int h[NC];
    if (threadIdx.x < NC) h[threadIdx.x] = 0;
    __syncthreads();
    for (int i = blockIdx.x * blockDim.x + threadIdx.x; i < n;
         i += gridDim.x * blockDim.x)
        atomicAdd(&h[cid[i]], 1);
    __syncthreads();
    if (threadIdx.x < NC) atomicAdd(&g_cnt[threadIdx.x], h[threadIdx.x]);
}

// ---------------- fused GEMM + ReLU + segment-sum ----------------
__device__ __forceinline__ void load_tile(const float* __restrict__ X,
                                          int rowBase, int n, int ks,
                                          int ar, int ac4, int br, int bq,
                                          float4 xa[2], uint4 wb[2]) {
#pragma unroll
    for (int h = 0; h < 2; h++) {
        int r = ar + h * 64;
        int grow = rowBase + r;
        if (grow < n)
            xa[h] = *reinterpret_cast<const float4*>(X + (size_t)grow * DIN +
                                                     ks * BK + ac4 * 4);
        else
            xa[h] = make_float4(0.f, 0.f, 0.f, 0.f);
    }
#pragma unroll
    for (int h = 0; h < 2; h++) {
        int r = br + h * 128;
        wb[h] = *reinterpret_cast<const uint4*>(g_w1bf + (size_t)r * DIN +
                                                ks * BK + bq * 8);
    }
}

__device__ __forceinline__ void store_tile(uint32_t* As, uint32_t* Bs,
                                           int ar, int ac4, int br, int bq,
                                           const float4 xa[2], const uint4 wb[2]) {
#pragma unroll
    for (int h = 0; h < 2; h++) {
        int r = ar + h * 64;
        __nv_bfloat162 p0 = __floats2bfloat162_rn(xa[h].x, xa[h].y);
        __nv_bfloat162 p1 = __floats2bfloat162_rn(xa[h].z, xa[h].w);
        As[r * SAU + ac4 * 2]     = *reinterpret_cast<const uint32_t*>(&p0);
        As[r * SAU + ac4 * 2 + 1] = *reinterpret_cast<const uint32_t*>(&p1);
    }
#pragma unroll
    for (int h = 0; h < 2; h++) {
        int r = br + h * 128;
        Bs[r * SAU + bq * 4 + 0] = wb[h].x;
        Bs[r * SAU + bq * 4 + 1] = wb[h].y;
        Bs[r * SAU + bq * 4 + 2] = wb[h].z;
        Bs[r * SAU + bq * 4 + 3] = wb[h].w;
    }
}

__global__ __launch_bounds__(NT)
void k_main(const float* __restrict__ X, const int* __restrict__ cid,
            const float* __restrict__ b1, int n)
{
    __shared__ __align__(16) uint32_t As[BM * SAU];
    __shared__ __align__(16) uint32_t Bs[BN * SAU];
    __shared__ float b1s[DH];
    __shared__ int   cids[BM];
    __shared__ float spart[NC * SPS];

    const int tid = threadIdx.x;
    const int rowBase = blockIdx.x * BM;

    for (int i = tid; i < NC * SPS; i += NT) spart[i] = 0.f;
    for (int i = tid; i < DH; i += NT) b1s[i] = b1[i];
    for (int i = tid; i < BM; i += NT) {
        int r = rowBase + i;
        cids[i] = (r < n) ? cid[r] : 0;
    }

    const int lane = tid & 31;
    const int warp = tid >> 5;
    const int g  = lane >> 2;
    const int tg = lane & 3;
    const int wm = warp & 3;   // 4 warps along M (warp tile 32 rows)
    const int wn = warp >> 2;  // 4 warps along N (warp tile 64 cols)

    float acc[2][8][4];
#pragma unroll
    for (int a = 0; a < 2; a++)
#pragma unroll
        for (int b = 0; b < 8; b++)
#pragma unroll
            for (int c = 0; c < 4; c++) acc[a][b][c] = 0.f;

    const int ar  = tid >> 3;  // 0..63  (x tile rows, 2 halves)
    const int ac4 = tid & 7;   // float4 column within BK
    const int br  = tid >> 2;  // 0..127 (W1 tile rows, 2 halves)
    const int bq  = tid & 3;   // uint4 column within BK

    float4 xa[2];
    uint4  wb[2];

    const int KSTEPS = DIN / BK;  // 32

    load_tile(X, rowBase, n, 0, ar, ac4, br, bq, xa, wb);
    store_tile(As, Bs, ar, ac4, br, bq, xa, wb);
    __syncthreads();

    for (int step = 0; step < KSTEPS; step++) {
        if (step + 1 < KSTEPS)
            load_tile(X, rowBase, n, step + 1, ar, ac4, br, bq, xa, wb);

#pragma unroll
        for (int kk = 0; kk < 2; kk++) {
            uint32_t af[2][4];
#pragma unroll
            for (int mt = 0; mt < 2; mt++) {
                int r0 = wm * 32 + mt * 16 + g;
                const uint32_t* base = As + r0 * SAU + kk * 8 + tg;
                af[mt][0] = base[0];
                af[mt][1] = base[8 * SAU];
                af[mt][2] = base[4];
                af[mt][3] = base[8 * SAU + 4];
            }
            uint32_t bf2[8][2];
#pragma unroll
            for (int nt = 0; nt < 8; nt++) {
                int c = wn * 64 + nt * 8 + g;
                const uint32_t* bb = Bs + c * SAU + kk * 8 + tg;
                bf2[nt][0] = bb[0];
                bf2[nt][1] = bb[4];
            }
#pragma unroll
            for (int mt = 0; mt < 2; mt++)
#pragma unroll
                for (int nt = 0; nt < 8; nt++)
                    asm volatile(
                        "mma.sync.aligned.m16n8k16.row.col.f32.bf16.bf16.f32 "
                        "{%0,%1,%2,%3}, {%4,%5,%6,%7}, {%8,%9}, {%0,%1,%2,%3};\n"
                        : "+f"(acc[mt][nt][0]), "+f"(acc[mt][nt][1]),
                          "+f"(acc[mt][nt][2]), "+f"(acc[mt][nt][3])
                        : "r"(af[mt][0]), "r"(af[mt][1]),
                          "r"(af[mt][2]), "r"(af[mt][3]),
                          "r"(bf2[nt][0]), "r"(bf2[nt][1]));
        }
        __syncthreads();
        if (step + 1 < KSTEPS) {
            store_tile(As, Bs, ar, ac4, br, bq, xa, wb);
            __syncthreads();
        }
    }

    // epilogue: bias + ReLU + per-cluster partial sums in smem
#pragma unroll
    for (int mt = 0; mt < 2; mt++) {
        int r0 = wm * 32 + mt * 16 + g;
        int r1 = r0 + 8;
        bool v0 = (rowBase + r0) < n;
        bool v1 = (rowBase + r1) < n;
        int c0 = cids[r0] * SPS;
        int c1 = cids[r1] * SPS;
#pragma unroll
        for (int nt = 0; nt < 8; nt++) {
            int c = wn * 64 + nt * 8 + 2 * tg;
            float t;
            t = acc[mt][nt][0] + b1s[c];
            if (v0 && t > 0.f) atomicAdd(&spart[c0 + c], t);
            t = acc[mt][nt][1] + b1s[c + 1];
            if (v0 && t > 0.f) atomicAdd(&spart[c0 + c + 1], t);
            t = acc[mt][nt][2] + b1s[c];
            if (v1 && t > 0.f) atomicAdd(&spart[c1 + c], t);
            t = acc[mt][nt][3] + b1s[c + 1];
            if (v1 && t > 0.f) atomicAdd(&spart[c1 + c + 1], t);
        }
    }
    __syncthreads();
    for (int i = tid; i < NC * DH; i += NT) {
        int c = i >> 8, j = i & 255;
        float v = spart[c * SPS + j];
        if (v != 0.f) atomicAdd(&g_csum[i], v);
    }
}

// ---------------- final small MLP + gated attention ----------------
__global__ void k_final(const float* __restrict__ Wf, const float* __restrict__ bfv,
                        const float* __restrict__ Wa, const float* __restrict__ ba,
                        const float* __restrict__ Wb, const float* __restrict__ bb,
                        const float* __restrict__ Wc, const float* __restrict__ bc,
                        float* __restrict__ out)
{
    __shared__ float hc[NC][DH];
    __shared__ float hp[NC][DH];
    __shared__ float ag[NC][DH];
    __shared__ float Avals[NC];
    __shared__ float wts[NC];

    const int tid = threadIdx.x;      // 256 threads
    const int lane = tid & 31;
    const int warp = tid >> 5;        // 8 warps

    for (int i = tid; i < NC * DH; i += 256) {
        int c = i >> 8;
        float cnt = fmaxf((float)g_cnt[c], 1.f);
        hc[c][i & 255] = g_csum[i] / cnt;
    }
    __syncthreads();

    // h_path[c][j] = relu(sum_k hc[c][k] * Wf[j][k] + bf[j]); warp handles j block
    for (int jj = 0; jj < 32; jj++) {
        int j = warp * 32 + jj;
        float p[NC];
#pragma unroll
        for (int c = 0; c < NC; c++) p[c] = 0.f;
        for (int i = 0; i < DH / 32; i++) {
            int k = i * 32 + lane;
            float w = Wf[j * DH + k];
#pragma unroll
            for (int c = 0; c < NC; c++) p[c] += w * hc[c][k];
        }
#pragma unroll
        for (int c = 0; c < NC; c++)
#pragma unroll
            for (int o = 16; o > 0; o >>= 1)
                p[c] += __shfl_xor_sync(0xffffffffu, p[c], o);
        if (lane == 0) {
#pragma unroll
            for (int c = 0; c < NC; c++)
                hp[c][j] = fmaxf(p[c] + bfv[j], 0.f);
        }
    }
    __syncthreads();

    // ag[c][j] = tanh(hp@Wa^T + ba) * sigmoid(hp@Wb^T + bb)
    for (int jj = 0; jj < 32; jj++) {
        int j = warp * 32 + jj;
        float pa[NC], pb[NC];
#pragma unroll
        for (int c = 0; c < NC; c++) { pa[c] = 0.f; pb[c] = 0.f; }
        for (int i = 0; i < DH / 32; i++) {
            int k = i * 32 + lane;
            float wa = Wa[j * DH + k];
            float wv = Wb[j * DH + k];
#pragma unroll
            for (int c = 0; c < NC; c++) {
                pa[c] += wa * hp[c][k];
                pb[c] += wv * hp[c][k];
            }
        }
#pragma unroll
        for (int c = 0; c < NC; c++) {
#pragma unroll
            for (int o = 16; o > 0; o >>= 1) {
                pa[c] += __shfl_xor_sync(0xffffffffu, pa[c], o);
                pb[c] += __shfl_xor_sync(0xffffffffu, pb[c], o);
            }
        }
        if (lane == 0) {
#pragma unroll
            for (int c = 0; c < NC; c++) {
                float av = tanhf(pa[c] + ba[j]);
                float gv = 1.f / (1.f + expf(-(pb[c] + bb[j])));
                ag[c][j] = av * gv;
            }
        }
    }
    __syncthreads();

    // A[c] = dot(ag[c], Wc) + bc
    if (warp < NC) {
        int c = warp;
        float p = 0.f;
        for (int i = 0; i < DH / 32; i++) {
            int k = i * 32 + lane;
            p += ag[c][k] * Wc[k];
        }
#pragma unroll
        for (int o = 16; o > 0; o >>= 1)
            p += __shfl_xor_sync(0xffffffffu, p, o);
        if (lane == 0) Avals[c] = p + bc[0];
    }
    __syncthreads();

    if (tid == 0) {
        float m = Avals[0];
        for (int c = 1; c < NC; c++) m = fmaxf(m, Avals[c]);
        float s = 0.f;
        for (int c = 0; c < NC; c++) { wts[c] = expf(Avals[c] - m); s += wts[c]; }
        float inv = 1.f / s;
        for (int c = 0; c < NC; c++) wts[c] *= inv;
    }
    __syncthreads();

    if (tid < DH) {
        float s = 0.f;
#pragma unroll
        for (int c = 0; c < NC; c++) s += wts[c] * hp[c][tid];
        out[tid] = s;
    }
}

extern "C" void kernel_launch(void* const* d_in, const int* in_sizes, int n_in,
                              void* d_out, int out_size)
{
    const float* X   = (const float*)d_in[0];
    const int*   cid = (const int*)d_in[1];
    const float* W1  = (const float*)d_in[2];
    const float* b1  = (const float*)d_in[3];
    const float* Wf  = (const float*)d_in[4];
    const float* bfv = (const float*)d_in[5];
    const float* Wa  = (const float*)d_in[6];
    const float* ba  = (const float*)d_in[7];
    const float* Wb  = (const float*)d_in[8];
    const float* bb  = (const float*)d_in[9];
    const float* Wc  = (const float*)d_in[10];
    const float* bc  = (const float*)d_in[11];
    float* out = (float*)d_out;
    const int n = in_sizes[1];  // N tokens (cluster_id count)

    void *p_csum = nullptr, *p_cnt = nullptr;
    cudaGetSymbolAddress(&p_csum, g_csum);
    cudaGetSymbolAddress(&p_cnt,  g_cnt);
    cudaMemsetAsync(p_csum, 0, sizeof(float) * NC * DH, 0);
    cudaMemsetAsync(p_cnt,  0, sizeof(int) * NC, 0);

    k_convert<<<256, 256>>>(W1);
    k_count<<<128, 256>>>(cid, n);

    int grid = (n + BM - 1) / BM;
    k_main<<<grid, NT>>>(X, cid, b1, n);
    k_final<<<1, 256>>>(Wf, bfv, Wa, ba, Wb, bb, Wc, bc, out);
}

// round 3
// speedup vs baseline: 1.3580x; 1.3580x over previous
#include <cuda_runtime.h>
#include <cuda_bf16.h>
#include <cstdint>

#define DIN 1024
#define DH  256
#define NC  8
#define NMAX 65536

#define BM 128
#define BN 256
#define BK 64
#define NT 512
#define CHUNKS (DIN / BK)   // 16
#define SPS 264

// ---------------- device scratch ----------------
__device__ float g_csum[NC * DH];
__device__ int   g_cnt[NC];
__device__ int   g_off[NC];
__device__ int   g_perm[NMAX];
__device__ int   g_scid[NMAX];
__device__ __align__(16) __nv_bfloat16 g_w1bf[DH * DIN];

// ---------------- helpers ----------------
__device__ __forceinline__ uint32_t smem_to_u32(const void* p) {
    uint32_t a;
    asm("{ .reg .u64 t; cvta.to.shared.u64 t, %1; cvt.u32.u64 %0, t; }"
        : "=r"(a) : "l"(p));
    return a;
}
#define CP_ASYNC16(dst, src) \
    asm volatile("cp.async.cg.shared.global [%0], [%1], 16;" :: "r"(dst), "l"(src) : "memory")
#define CP_COMMIT() asm volatile("cp.async.commit_group;" ::: "memory")
#define CP_WAIT0()  asm volatile("cp.async.wait_group 0;" ::: "memory")
#define LDSM4(r0, r1, r2, r3, a) \
    asm volatile("ldmatrix.sync.aligned.m8n8.x4.shared.b16 {%0,%1,%2,%3}, [%4];" \
                 : "=r"(r0), "=r"(r1), "=r"(r2), "=r"(r3) : "r"(a))
#define MMA16816(d0,d1,d2,d3, a0,a1,a2,a3, b0,b1) \
    asm volatile("mma.sync.aligned.m16n8k16.row.col.f32.bf16.bf16.f32 " \
                 "{%0,%1,%2,%3}, {%4,%5,%6,%7}, {%8,%9}, {%0,%1,%2,%3};\n" \
                 : "+f"(d0), "+f"(d1), "+f"(d2), "+f"(d3) \
                 : "r"(a0), "r"(a1), "r"(a2), "r"(a3), "r"(b0), "r"(b1))

// ---------------- k_prep: W1->bf16 (blocks 0..255) + cluster count (256..383) ----------------
__global__ void k_prep(const float* __restrict__ W1, const int* __restrict__ cid, int n) {
    if (blockIdx.x < 256) {
        int base = blockIdx.x * 1024 + threadIdx.x;
#pragma unroll
        for (int t = 0; t < 4; t++) {
            int i = base + t * 256;
            g_w1bf[i] = __float2bfloat16(W1[i]);
        }
    } else {
        __shared__ int h[NC];
        if (threadIdx.x < NC) h[threadIdx.x] = 0;
        __syncthreads();
        int b = blockIdx.x - 256;
        for (int i = b * 256 + threadIdx.x; i < n; i += 128 * 256)
            atomicAdd(&h[cid[i]], 1);
        __syncthreads();
        if (threadIdx.x < NC) atomicAdd(&g_cnt[threadIdx.x], h[threadIdx.x]);
    }
}

__global__ void k_prefix() {
    if (threadIdx.x == 0) {
        int s = 0;
        for (int c = 0; c < NC; c++) { g_off[c] = s; s += g_cnt[c]; }
    }
}

__global__ void k_scatter(const int* __restrict__ cid, int n) {
    __shared__ int lh[NC], base[NC], lr[NC];
    int i = blockIdx.x * 256 + threadIdx.x;
    int c = (i < n) ? cid[i] : -1;
    if (threadIdx.x < NC) { lh[threadIdx.x] = 0; lr[threadIdx.x] = 0; }
    __syncthreads();
    if (c >= 0) atomicAdd(&lh[c], 1);
    __syncthreads();
    if (threadIdx.x < NC && lh[threadIdx.x] > 0)
        base[threadIdx.x] = atomicAdd(&g_off[threadIdx.x], lh[threadIdx.x]);
    __syncthreads();
    if (c >= 0) {
        int r = atomicAdd(&lr[c], 1);
        int slot = base[c] + r;
        g_perm[slot] = i;
        g_scid[slot] = c;
    }
}

// ---------------- k_main: mma.sync GEMM + ReLU + segment-sum ----------------
// dynamic smem layout (bytes)
#define OFF_B1S  0          // 1024
#define OFF_CIDS 1024       // 512
#define OFF_PERM 1536       // 512
#define OFF_SPRT 2048       // NC*SPS*4 = 8448 -> ends 10496
#define OFF_A    12288      // 2 stages x 16384
#define OFF_B    45056      // 2 stages x 32768
#define A_STAGE  16384
#define B_STAGE  32768
#define SMEM_BYTES 110592

__global__ __launch_bounds__(NT, 1)
void k_main(const float* __restrict__ X, const float* __restrict__ b1, int n)
{
    extern __shared__ __align__(1024) char smem[];
    const uint32_t sb = smem_to_u32(smem);
    const int tid  = threadIdx.x;
    const int lane = tid & 31;
    const int wid  = tid >> 5;
    const int wm   = wid & 3;      // 4 warps along M (32 rows each)
    const int wn   = wid >> 2;     // 4 warps along N (64 cols each)
    const int rowBase = blockIdx.x * BM;

    float* b1s   = (float*)(smem + OFF_B1S);
    int*   cids  = (int*)(smem + OFF_CIDS);
    int*   perms = (int*)(smem + OFF_PERM);
    float* spart = (float*)(smem + OFF_SPRT);

    for (int i = tid; i < NC * SPS; i += NT) spart[i] = 0.f;
    if (tid < DH) b1s[tid] = b1[tid];
    if (tid < BM) {
        int g = rowBase + tid;
        perms[tid] = (g < n) ? g_perm[g] : 0;
        cids[tid]  = (g < n) ? g_scid[g] : 0;
    }
    __syncthreads();

    // ---- per-thread load maps ----
    const int xrow = tid >> 2;           // 0..127
    const int xseg = tid & 3;            // 16 floats each
    const bool xvalid = (rowBase + xrow) < n;
    const float* xsrc0 = X + (size_t)perms[xrow] * DIN + xseg * 16;
    const uint32_t xdst = sb + OFF_A + xrow * 128 +
                          ((xseg * 32) ^ ((xrow & 7) << 4));
    const uint32_t xdst2 = sb + OFF_A + xrow * 128 +
                           (((xseg * 32) + 16) ^ ((xrow & 7) << 4));

    const int wrow = tid >> 1;           // 0..255
    const int wseg = tid & 1;            // 32 elems each
    const __nv_bfloat16* wsrc0 = g_w1bf + (size_t)wrow * DIN + wseg * 32;
    uint32_t wdst[4];
#pragma unroll
    for (int q = 0; q < 4; q++)
        wdst[q] = sb + OFF_B + wrow * 128 +
                  ((wseg * 64 + q * 16) ^ ((wrow & 7) << 4));

    // ---- per-lane ldmatrix pointers (stage 0) ----
    uint32_t aPtr[2], bPtr[4];
    {
        int jm  = lane & 7;
        int sel8 = (lane >> 3) & 1;   // +8 rows
        int selk = (lane >> 4) & 1;   // k8..15
#pragma unroll
        for (int mt = 0; mt < 2; mt++) {
            int r = wm * 32 + mt * 16 + jm + sel8 * 8;
            aPtr[mt] = sb + OFF_A + r * 128 + ((selk * 16) ^ ((r & 7) << 4));
        }
        int jn  = lane & 7;
        int selk2 = (lane >> 3) & 1;  // k8..15
        int seln  = (lane >> 4) & 1;  // +8 n
#pragma unroll
        for (int p = 0; p < 4; p++) {
            int r = wn * 64 + p * 16 + jn + seln * 8;
            bPtr[p] = sb + OFF_B + r * 128 + ((selk2 * 16) ^ ((r & 7) << 4));
        }
    }

    float acc[2][8][4];
#pragma unroll
    for (int a = 0; a < 2; a++)
#pragma unroll
        for (int b = 0; b < 8; b++)
#pragma unroll
            for (int c = 0; c < 4; c++) acc[a][b][c] = 0.f;

    // ---- X load+convert helper (to registers) ----
    auto ldx = [&](int chunk, uint32_t h[8]) {
        float4 f[4];
        if (xvalid) {
            const float4* p = (const float4*)(xsrc0 + chunk * BK);
#pragma unroll
            for (int t = 0; t < 4; t++) f[t] = p[t];
        } else {
#pragma unroll
            for (int t = 0; t < 4; t++) f[t] = make_float4(0.f, 0.f, 0.f, 0.f);
        }
#pragma unroll
        for (int t = 0; t < 4; t++) {
            __nv_bfloat162 lo = __floats2bfloat162_rn(f[t].x, f[t].y);
            __nv_bfloat162 hi = __floats2bfloat162_rn(f[t].z, f[t].w);
            h[t * 2]     = *(uint32_t*)&lo;
            h[t * 2 + 1] = *(uint32_t*)&hi;
        }
    };
    auto stx = [&](int stage, const uint32_t h[8]) {
        *(uint4*)(size_t)(xdst  + stage * A_STAGE) = make_uint4(h[0], h[1], h[2], h[3]);
        *(uint4*)(size_t)(xdst2 + stage * A_STAGE) = make_uint4(h[4], h[5], h[6], h[7]);
    };
    // NOTE: smem generic store via u32 address: use inline asm instead (safe)
    auto stx_asm = [&](int stage, const uint32_t h[8]) {
        uint32_t d0 = xdst + stage * A_STAGE, d1 = xdst2 + stage * A_STAGE;
        asm volatile("st.shared.v4.b32 [%0], {%1,%2,%3,%4};" ::
                     "r"(d0), "r"(h[0]), "r"(h[1]), "r"(h[2]), "r"(h[3]) : "memory");
        asm volatile("st.shared.v4.b32 [%0], {%1,%2,%3,%4};" ::
                     "r"(d1), "r"(h[4]), "r"(h[5]), "r"(h[6]), "r"(h[7]) : "memory");
    };
    (void)stx;
    auto ldw = [&](int chunk, int stage) {
        const char* s = (const char*)(wsrc0 + chunk * BK);
#pragma unroll
        for (int q = 0; q < 4; q++)
            CP_ASYNC16(wdst[q] + stage * B_STAGE, s + q * 16);
        CP_COMMIT();
    };

    auto compute = [&](int stage) {
        const uint32_t aOfs = stage * A_STAGE;
        const uint32_t bOfs = stage * B_STAGE;
#pragma unroll
        for (int kk = 0; kk < 4; kk++) {
            uint32_t af[2][4];
#pragma unroll
            for (int mt = 0; mt < 2; mt++)
                LDSM4(af[mt][0], af[mt][1], af[mt][2], af[mt][3],
                      (aPtr[mt] + aOfs) ^ (kk << 5));
            uint32_t bf[4][4];
#pragma unroll
            for (int p = 0; p < 4; p++)
                LDSM4(bf[p][0], bf[p][1], bf[p][2], bf[p][3],
                      (bPtr[p] + bOfs) ^ (kk << 5));
#pragma unroll
            for (int mt = 0; mt < 2; mt++)
#pragma unroll
                for (int p = 0; p < 4; p++) {
                    MMA16816(acc[mt][2*p][0],   acc[mt][2*p][1],
                             acc[mt][2*p][2],   acc[mt][2*p][3],
                             af[mt][0], af[mt][1], af[mt][2], af[mt][3],
                             bf[p][0], bf[p][1]);
                    MMA16816(acc[mt][2*p+1][0], acc[mt][2*p+1][1],
                             acc[mt][2*p+1][2], acc[mt][2*p+1][3],
                             af[mt][0], af[mt][1], af[mt][2], af[mt][3],
                             bf[p][2], bf[p][3]);
                }
        }
    };

    // ---- prologue ----
    uint32_t h0[8];
    ldw(0, 0);
    ldx(0, h0);
    stx_asm(0, h0);

    // ---- main loop (double-buffered) ----
    for (int chunk = 0; chunk < CHUNKS; chunk++) {
        const int cur = chunk & 1;
        const int nxt = cur ^ 1;
        const bool more = (chunk + 1) < CHUNKS;
        uint32_t h2[8];
        if (more) ldx(chunk + 1, h2);
        CP_WAIT0();
        __syncthreads();
        if (more) {
            ldw(chunk + 1, nxt);
            stx_asm(nxt, h2);
        }
        compute(cur);
    }

    // ---- epilogue: bias + ReLU + segment-sum ----
    const int g  = lane >> 2;
    const int tg = lane & 3;
    const bool uni = (cids[0] == cids[BM - 1]) && (rowBase + BM <= n);

    if (uni) {
        const int cl = cids[0];
#pragma unroll
        for (int nt = 0; nt < 8; nt++) {
            int c = wn * 64 + nt * 8 + tg * 2;
            float s0 = 0.f, s1 = 0.f;
#pragma unroll
            for (int mt = 0; mt < 2; mt++) {
                s0 += fmaxf(acc[mt][nt][0] + b1s[c], 0.f)
                    + fmaxf(acc[mt][nt][2] + b1s[c], 0.f);
                s1 += fmaxf(acc[mt][nt][1] + b1s[c + 1], 0.f)
                    + fmaxf(acc[mt][nt][3] + b1s[c + 1], 0.f);
            }
#pragma unroll
            for (int o = 4; o < 32; o <<= 1) {
                s0 += __shfl_xor_sync(0xffffffffu, s0, o);
                s1 += __shfl_xor_sync(0xffffffffu, s1, o);
            }
            if (g == 0) {
                atomicAdd(&spart[cl * SPS + c], s0);
                atomicAdd(&spart[cl * SPS + c + 1], s1);
            }
        }
    } else {
#pragma unroll
        for (int mt = 0; mt < 2; mt++) {
            int r0 = wm * 32 + mt * 16 + g;
            int r1 = r0 + 8;
            bool v0 = (rowBase + r0) < n;
            bool v1 = (rowBase + r1) < n;
            int c0 = cids[r0] * SPS;
            int c1 = cids[r1] * SPS;
#pragma unroll
            for (int nt = 0; nt < 8; nt++) {
                int c = wn * 64 + nt * 8 + tg * 2;
                float t;
                t = acc[mt][nt][0] + b1s[c];
                if (v0 && t > 0.f) atomicAdd(&spart[c0 + c], t);
                t = acc[mt][nt][1] + b1s[c + 1];
                if (v0 && t > 0.f) atomicAdd(&spart[c0 + c + 1], t);
                t = acc[mt][nt][2] + b1s[c];
                if (v1 && t > 0.f) atomicAdd(&spart[c1 + c], t);
                t = acc[mt][nt][3] + b1s[c + 1];
                if (v1 && t > 0.f) atomicAdd(&spart[c1 + c + 1], t);
            }
        }
    }
    __syncthreads();
    for (int i = tid; i < NC * DH; i += NT) {
        int c = i >> 8, j = i & 255;
        float v = spart[c * SPS + j];
        if (v != 0.f) atomicAdd(&g_csum[i], v);
    }
}

// ---------------- k_final: small MLP + gated attention ----------------
__global__ __launch_bounds__(512) void k_final(
    const float* __restrict__ Wf, const float* __restrict__ bfv,
    const float* __restrict__ Wa, const float* __restrict__ ba,
    const float* __restrict__ Wb, const float* __restrict__ bb,
    const float* __restrict__ Wc, const float* __restrict__ bc,
    float* __restrict__ out)
{
    __shared__ float hc[NC][DH];
    __shared__ float hp[NC][DH];
    __shared__ float pA[NC][DH];
    __shared__ float pB[NC][DH];
    __shared__ float asum[NC], wts[NC];

    const int tid = threadIdx.x;
    const int j = tid & 255;
    const int hf = tid >> 8;
    const int lane = tid & 31;

    for (int i = tid; i < NC * DH; i += 512) {
        int c = i >> 8;
        hc[c][i & 255] = g_csum[i] / fmaxf((float)g_cnt[c], 1.f);
    }
    if (tid < NC) asum[tid] = 0.f;
    __syncthreads();

    {
        float p[NC];
#pragma unroll
        for (int c = 0; c < NC; c++) p[c] = 0.f;
        const float4* wrow = (const float4*)(Wf + j * DH + hf * 128);
#pragma unroll 4
        for (int k4 = 0; k4 < 32; k4++) {
            float4 w = wrow[k4];
            int k = hf * 128 + k4 * 4;
#pragma unroll
            for (int c = 0; c < NC; c++) {
                float4 h4 = *(const float4*)&hc[c][k];
                p[c] += w.x * h4.x + w.y * h4.y + w.z * h4.z + w.w * h4.w;
            }
        }
        float* dst = hf ? &pB[0][0] : &pA[0][0];
#pragma unroll
        for (int c = 0; c < NC; c++) dst[c * DH + j] = p[c];
    }
    __syncthreads();

    float hpj[NC];
    if (hf == 0) {
#pragma unroll
        for (int c = 0; c < NC; c++) {
            hpj[c] = fmaxf(pA[c][j] + pB[c][j] + bfv[j], 0.f);
            hp[c][j] = hpj[c];
        }
    }
    __syncthreads();

    {
        const float* w2 = (hf ? Wb : Wa) + j * DH;
        float q[NC];
#pragma unroll
        for (int c = 0; c < NC; c++) q[c] = 0.f;
#pragma unroll 4
        for (int k4 = 0; k4 < 64; k4++) {
            float4 w = ((const float4*)w2)[k4];
#pragma unroll
            for (int c = 0; c < NC; c++) {
                float4 h4 = *(const float4*)&hp[c][k4 * 4];
                q[c] += w.x * h4.x + w.y * h4.y + w.z * h4.z + w.w * h4.w;
            }
        }
        float* dst = hf ? &pB[0][0] : &pA[0][0];
#pragma unroll
        for (int c = 0; c < NC; c++) dst[c * DH + j] = q[c];
    }
    __syncthreads();

    if (hf == 0) {
        float wcj = Wc[j];
#pragma unroll
        for (int c = 0; c < NC; c++) {
            float av = tanhf(pA[c][j] + ba[j]);
            float gv = 1.f / (1.f + __expf(-(pB[c][j] + bb[j])));
            float v = av * gv * wcj;
#pragma unroll
            for (int o = 16; o > 0; o >>= 1)
                v += __shfl_xor_sync(0xffffffffu, v, o);
            if (lane == 0) atomicAdd(&asum[c], v);
        }
    }
    __syncthreads();

    if (tid == 0) {
        float m = -1e30f;
        for (int c = 0; c < NC; c++) m = fmaxf(m, asum[c] + bc[0]);
        float s = 0.f;
        for (int c = 0; c < NC; c++) { wts[c] = __expf(asum[c] + bc[0] - m); s += wts[c]; }
        float inv = 1.f / s;
        for (int c = 0; c < NC; c++) wts[c] *= inv;
    }
    __syncthreads();

    if (hf == 0) {
        float s = 0.f;
#pragma unroll
        for (int c = 0; c < NC; c++) s += wts[c] * hpj[c];
        out[j] = s;
    }
}

// ---------------- launch ----------------
extern "C" void kernel_launch(void* const* d_in, const int* in_sizes, int n_in,
                              void* d_out, int out_size)
{
    const float* X   = (const float*)d_in[0];
    const int*   cid = (const int*)d_in[1];
    const float* W1  = (const float*)d_in[2];
    const float* b1  = (const float*)d_in[3];
    const float* Wf  = (const float*)d_in[4];
    const float* bfv = (const float*)d_in[5];
    const float* Wa  = (const float*)d_in[6];
    const float* ba  = (const float*)d_in[7];
    const float* Wb  = (const float*)d_in[8];
    const float* bb  = (const float*)d_in[9];
    const float* Wc  = (const float*)d_in[10];
    const float* bc  = (const float*)d_in[11];
    float* out = (float*)d_out;
    const int n = in_sizes[1];

    cudaFuncSetAttribute(k_main, cudaFuncAttributeMaxDynamicSharedMemorySize, SMEM_BYTES);

    void *p_csum = nullptr, *p_cnt = nullptr;
    cudaGetSymbolAddress(&p_csum, g_csum);
    cudaGetSymbolAddress(&p_cnt,  g_cnt);
    cudaMemsetAsync(p_csum, 0, sizeof(float) * NC * DH, 0);    // launch 1
    cudaMemsetAsync(p_cnt,  0, sizeof(int) * NC, 0);           // launch 2

    k_prep<<<384, 256>>>(W1, cid, n);                          // launch 3
    k_prefix<<<1, 32>>>();                                     // launch 4
    int sg = (n + 255) / 256;
    k_scatter<<<sg, 256>>>(cid, n);                            // launch 5

    int grid = (n + BM - 1) / BM;
    k_main<<<grid, NT, SMEM_BYTES>>>(X, b1, n);                // launch 6 (profiled)
    k_final<<<1, 512>>>(Wf, bfv, Wa, ba, Wb, bb, Wc, bc, out); // launch 7
}